// round 9
// baseline (speedup 1.0000x reference)
#include <cuda_runtime.h>
#include <cuda_bf16.h>
#include <math.h>
#include <stdint.h>

// Problem sizes (fixed)
#define BATCH 8
#define SEQ   2048
#define DIM   1024
#define MTOT  (BATCH*SEQ)
#define PLANE (SEQ*DIM)
#define TEN   ((size_t)BATCH*PLANE)

// ---------------- device scratch (no allocations allowed) -------------------
// All tf32 scratch tensors are stored k-PERMUTED: within each group of 8 along
// the contraction axis, element k sits at position 2*(k&3) + (k>>2).
__device__ float g_scores[(size_t)BATCH * SEQ * SEQ];   // S normal; after softmax: perm tf32 P
__device__ float g_Wt[(size_t)3 * DIM * DIM];           // W^T [n][k] perm tf32
__device__ float g_Vt[(size_t)BATCH * DIM * SEQ];       // V^T [n][k] perm tf32
__device__ float g_Xt[(size_t)MTOT * DIM];              // X perm tf32
__device__ float g_Qt[(size_t)MTOT * DIM];              // Q perm tf32
__device__ float g_Kt[(size_t)MTOT * DIM];              // K perm tf32

__device__ __forceinline__ int perm8(int k) { return 2 * (k & 3) + ((k >> 2) & 1); }

// ---------------- helpers ----------------------------------------------------
__device__ __forceinline__ uint32_t smem_u32(const void* p) {
    uint32_t a;
    asm("{ .reg .u64 t; cvta.to.shared.u64 t, %1; cvt.u32.u64 %0, t; }" : "=r"(a) : "l"(p));
    return a;
}
__device__ __forceinline__ void cp16(uint32_t s, const void* g) {
    asm volatile("cp.async.cg.shared.global [%0], [%1], 16;" :: "r"(s), "l"(g));
}
__device__ __forceinline__ void cp_commit() { asm volatile("cp.async.commit_group;" ::: "memory"); }
template <int N> __device__ __forceinline__ void cp_wait() {
    asm volatile("cp.async.wait_group %0;" :: "n"(N) : "memory");
}
__device__ __forceinline__ float f2tf(float x) {
    uint32_t u;
    asm("cvt.rna.tf32.f32 %0, %1;" : "=r"(u) : "f"(x));
    return __uint_as_float(u);
}
__device__ __forceinline__ void mma_tf32(float* c, const uint32_t* a, const uint32_t* b) {
    asm volatile(
        "mma.sync.aligned.m16n8k8.row.col.f32.tf32.tf32.f32 "
        "{%0,%1,%2,%3}, {%4,%5,%6,%7}, {%8,%9}, {%0,%1,%2,%3};"
        : "+f"(c[0]), "+f"(c[1]), "+f"(c[2]), "+f"(c[3])
        : "r"(a[0]), "r"(a[1]), "r"(a[2]), "r"(a[3]), "r"(b[0]), "r"(b[1]));
}

// ---------------- GEMM config ------------------------------------------------
#define BM 128
#define BN 128
#define BKF 32
#define PITCH 40                 // stride%32 = 8 banks -> conflict-free LDS.64
#define STAGES 3
#define ASTG (BM*PITCH)
#define BSTG (BN*PITCH)
#define SMEM_TOTAL (STAGES*(ASTG+BSTG)*4)   // 122,880 B -> 2 CTAs/SM

// 128 threads = 4 warps (2 along M x 2 along N), each owns a 64x64 sub-tile.
// MODE 0: QKV  C = Xt * Wt^T
// MODE 1: S    C = Qt * Kt^T (causal blocks, scaled)
// MODE 2: O    C = P  * Vt^T (causal K length)
template <int MODE>
__global__ __launch_bounds__(128, 2)
void gemm_tc(float* __restrict__ out)
{
    const int bx = blockIdx.x, by = blockIdx.y, bz = blockIdx.z;
    if (MODE == 1 && bx > by) return;

    const float *A, *B;
    float *C;
    int lda, ldb, ldc, KT;
    float scale = 1.f;

    if (MODE == 0) {
        A = g_Xt + (size_t)by * BM * DIM;                           lda = DIM;
        B = g_Wt + (size_t)bz * DIM * DIM + (size_t)bx * BN * DIM;  ldb = DIM;
        C = out + (size_t)(1 + bz) * TEN + (size_t)by * BM * DIM + bx * BN; ldc = DIM;
        KT = DIM / BKF;
    } else if (MODE == 1) {
        A = g_Qt + (size_t)bz * PLANE + (size_t)by * BM * DIM;      lda = DIM;
        B = g_Kt + (size_t)bz * PLANE + (size_t)bx * BN * DIM;      ldb = DIM;
        C = g_scores + (size_t)bz * SEQ * SEQ + (size_t)by * BM * SEQ + bx * BN; ldc = SEQ;
        KT = DIM / BKF;
        scale = 0.03125f;
    } else {
        A = g_scores + (size_t)bz * SEQ * SEQ + (size_t)by * BM * SEQ;  lda = SEQ;
        B = g_Vt + (size_t)bz * DIM * SEQ + (size_t)bx * BN * SEQ;      ldb = SEQ;
        C = out + (size_t)bz * PLANE + (size_t)by * BM * DIM + bx * BN; ldc = DIM;
        KT = (by + 1) * (BM / BKF);
    }

    extern __shared__ float sm[];
    const uint32_t sb = smem_u32(sm);
    const int tid = threadIdx.x;
    const int lane = tid & 31;
    const int warp = tid >> 5;
    const int warpM = warp & 1;       // 2 warps along M (64 rows)
    const int warpN = warp >> 1;      // 2 warps along N (64 cols)

    float acc[4][8][4];
#pragma unroll
    for (int mt = 0; mt < 4; mt++)
#pragma unroll
        for (int nt = 0; nt < 8; nt++)
#pragma unroll
            for (int i = 0; i < 4; i++) acc[mt][nt][i] = 0.f;

    auto load_stage = [&](int st, int k0) {
        const uint32_t sA = sb + (uint32_t)(st * ASTG) * 4;
        const uint32_t sB = sb + (uint32_t)((STAGES * ASTG) + st * BSTG) * 4;
#pragma unroll
        for (int i = 0; i < 8; i++) {
            int ci = tid + i * 128;
            int r = ci >> 3, ch = ci & 7;
            cp16(sA + (uint32_t)(r * PITCH + ch * 4) * 4, A + (size_t)r * lda + k0 + ch * 4);
        }
#pragma unroll
        for (int i = 0; i < 8; i++) {
            int ci = tid + i * 128;
            int r = ci >> 3, ch = ci & 7;
            cp16(sB + (uint32_t)(r * PITCH + ch * 4) * 4, B + (size_t)r * ldb + k0 + ch * 4);
        }
    };

#pragma unroll
    for (int p = 0; p < STAGES - 1; p++) {
        load_stage(p, p * BKF);
        cp_commit();
    }

    for (int it = 0; it < KT; ++it) {
        cp_wait<STAGES - 2>();
        __syncthreads();

        const int nx = it + STAGES - 1;
        if (nx < KT) load_stage(nx % STAGES, nx * BKF);
        cp_commit();

        const int s = it % STAGES;
        const float* sAf = sm + s * ASTG;
        const float* sBf = sm + STAGES * ASTG + s * BSTG;

#pragma unroll
        for (int k8 = 0; k8 < BKF / 8; k8++) {
            // permuted layout: logical cols (c, c+4), c = k8*8 + (lane&3),
            // sit adjacently at offset k8*8 + 2*(lane&3) -> one LDS.64 each.
            const int co = k8 * 8 + 2 * (lane & 3);
            uint32_t af[4][4];
            uint32_t bf[8][2];
            const int r0 = warpM * 64 + (lane >> 2);
#pragma unroll
            for (int mt = 0; mt < 4; mt++) {
                const int rr = r0 + mt * 16;
                uint2 q0 = *(const uint2*)(sAf + rr * PITCH + co);
                uint2 q1 = *(const uint2*)(sAf + (rr + 8) * PITCH + co);
                af[mt][0] = q0.x; af[mt][1] = q1.x; af[mt][2] = q0.y; af[mt][3] = q1.y;
            }
            const int n0 = warpN * 64 + (lane >> 2);
#pragma unroll
            for (int nt = 0; nt < 8; nt++) {
                uint2 qb = *(const uint2*)(sBf + (n0 + nt * 8) * PITCH + co);
                bf[nt][0] = qb.x; bf[nt][1] = qb.y;
            }
#pragma unroll
            for (int mt = 0; mt < 4; mt++)
#pragma unroll
                for (int nt = 0; nt < 8; nt++)
                    mma_tf32(acc[mt][nt], af[mt], bf[nt]);
        }
        __syncthreads();
    }

    // ---- epilogue ----
    const int rbase = warpM * 64 + (lane >> 2);
    const int cbase = warpN * 64 + 2 * (lane & 3);
#pragma unroll
    for (int mt = 0; mt < 4; mt++) {
#pragma unroll
        for (int nt = 0; nt < 8; nt++) {
            const int row = rbase + mt * 16;
            const int col = cbase + nt * 8;
            float2 v0 = {acc[mt][nt][0] * scale, acc[mt][nt][1] * scale};
            float2 v1 = {acc[mt][nt][2] * scale, acc[mt][nt][3] * scale};
            *(float2*)(C + (size_t)row * ldc + col)       = v0;
            *(float2*)(C + (size_t)(row + 8) * ldc + col) = v1;

            if (MODE == 0 && bz < 2) {   // emit k-permuted tf32 Q / K
                float* T = (bz == 0 ? g_Qt : g_Kt) +
                           (size_t)(by * BM + row) * DIM + bx * BN + (col & ~7);
                const int p0 = perm8(col & 7), p1 = perm8((col + 1) & 7);
                T[p0] = f2tf(v0.x);
                T[p1] = f2tf(v0.y);
                (T + (size_t)8 * DIM)[p0] = f2tf(v1.x);
                (T + (size_t)8 * DIM)[p1] = f2tf(v1.y);
            }
        }
    }
}

// ---------------- producers (all emit k-permuted tf32) -----------------------
__global__ __launch_bounds__(256)
void cvt_x(const float* __restrict__ X)
{
    size_t i = ((size_t)blockIdx.x * 256 + threadIdx.x) * 4;
    float4 v = *(const float4*)(X + i);
    float* dst = g_Xt + (i & ~(size_t)7);
    const int k0 = (int)(i & 7);
    dst[perm8(k0 + 0)] = f2tf(v.x);
    dst[perm8(k0 + 1)] = f2tf(v.y);
    dst[perm8(k0 + 2)] = f2tf(v.z);
    dst[perm8(k0 + 3)] = f2tf(v.w);
}

__global__ __launch_bounds__(256)
void transpose_w(const float* __restrict__ Wq, const float* __restrict__ Wk,
                 const float* __restrict__ Wv)
{
    __shared__ float t[32][33];
    const int w = blockIdx.z;
    const float* W = (w == 0) ? Wq : (w == 1) ? Wk : Wv;
    float* Wt = g_Wt + (size_t)w * DIM * DIM;
    const int n0 = blockIdx.x * 32, k0 = blockIdx.y * 32;
    const int tx = threadIdx.x & 31, ty = threadIdx.x >> 5;
#pragma unroll
    for (int j = 0; j < 4; j++)
        t[ty * 4 + j][tx] = W[(size_t)(k0 + ty * 4 + j) * DIM + n0 + tx];
    __syncthreads();
    const int kp = k0 + (tx & ~7) + perm8(tx & 7);
#pragma unroll
    for (int j = 0; j < 4; j++)
        Wt[(size_t)(n0 + ty * 4 + j) * DIM + kp] = f2tf(t[tx][ty * 4 + j]);
}

__global__ __launch_bounds__(256)
void transpose_v(const float* __restrict__ out)
{
    __shared__ float t[32][33];
    const int b = blockIdx.z;
    const float* V = out + 3 * TEN + (size_t)b * PLANE;   // [S][D]
    float* Vt = g_Vt + (size_t)b * DIM * SEQ;             // [D][S] perm tf32
    const int s0 = blockIdx.x * 32, a0 = blockIdx.y * 32;
    const int tx = threadIdx.x & 31, ty = threadIdx.x >> 5;
#pragma unroll
    for (int j = 0; j < 4; j++)
        t[ty * 4 + j][tx] = V[(size_t)(s0 + ty * 4 + j) * DIM + a0 + tx];
    __syncthreads();
    const int sp = s0 + (tx & ~7) + perm8(tx & 7);
#pragma unroll
    for (int j = 0; j < 4; j++)
        Vt[(size_t)(a0 + ty * 4 + j) * SEQ + sp] = f2tf(t[tx][ty * 4 + j]);
}

// ---------------- softmax (reads normal S, writes k-permuted tf32 P) ---------
__global__ __launch_bounds__(256)
void softmax_rows()
{
    __shared__ float row[SEQ];
    __shared__ float red[8];
    const int q = blockIdx.x, b = blockIdx.y, tid = threadIdx.x;
    const int lane = tid & 31, warp = tid >> 5;
    float* Srow = g_scores + (size_t)b * SEQ * SEQ + (size_t)q * SEQ;
    const int L = q + 1;
    const int kend = ((q >> 7) + 1) << 7;
    const int L4 = L >> 2;

    float mx = -INFINITY;
    const float4* S4 = (const float4*)Srow;
    for (int i = tid; i < L4; i += 256) {
        float4 v = S4[i];
        *(float4*)&row[i * 4] = v;
        mx = fmaxf(fmaxf(mx, fmaxf(v.x, v.y)), fmaxf(v.z, v.w));
    }
    if (L4 * 4 + tid < L) {
        float v = Srow[L4 * 4 + tid];
        row[L4 * 4 + tid] = v;
        mx = fmaxf(mx, v);
    }
#pragma unroll
    for (int o = 16; o > 0; o >>= 1) mx = fmaxf(mx, __shfl_xor_sync(~0u, mx, o));
    if (lane == 0) red[warp] = mx;
    __syncthreads();
    mx = red[0];
#pragma unroll
    for (int w2 = 1; w2 < 8; w2++) mx = fmaxf(mx, red[w2]);
    __syncthreads();

    float sum = 0.f;
    for (int i = tid; i < L4; i += 256) {
        float4 v = *(float4*)&row[i * 4];
        v.x = __expf(v.x - mx); v.y = __expf(v.y - mx);
        v.z = __expf(v.z - mx); v.w = __expf(v.w - mx);
        *(float4*)&row[i * 4] = v;
        sum += v.x + v.y + v.z + v.w;
    }
    if (L4 * 4 + tid < L) {
        float e = __expf(row[L4 * 4 + tid] - mx);
        row[L4 * 4 + tid] = e;
        sum += e;
    }
#pragma unroll
    for (int o = 16; o > 0; o >>= 1) sum += __shfl_xor_sync(~0u, sum, o);
    if (lane == 0) red[warp] = sum;
    __syncthreads();
    sum = 0.f;
#pragma unroll
    for (int w2 = 0; w2 < 8; w2++) sum += red[w2];
    const float inv = 1.f / sum;

    // permuted writes; perm is a bijection per 8-group and [0,kend) covers
    // whole groups, so every slot gets written exactly once.
    for (int i = tid; i < L; i += 256)
        Srow[(i & ~7) + perm8(i & 7)] = f2tf(row[i] * inv);
    for (int i = L + tid; i < kend; i += 256)
        Srow[(i & ~7) + perm8(i & 7)] = 0.f;
}

// ---------------- launch -----------------------------------------------------
extern "C" void kernel_launch(void* const* d_in, const int* in_sizes, int n_in,
                              void* d_out, int out_size)
{
    const float* X  = (const float*)d_in[0];
    const float* Wq = (const float*)d_in[1];
    const float* Wk = (const float*)d_in[2];
    const float* Wv = (const float*)d_in[3];
    float* out = (float*)d_out;

    static bool attr_done = false;
    if (!attr_done) {
        cudaFuncSetAttribute(gemm_tc<0>, cudaFuncAttributeMaxDynamicSharedMemorySize, SMEM_TOTAL);
        cudaFuncSetAttribute(gemm_tc<1>, cudaFuncAttributeMaxDynamicSharedMemorySize, SMEM_TOTAL);
        cudaFuncSetAttribute(gemm_tc<2>, cudaFuncAttributeMaxDynamicSharedMemorySize, SMEM_TOTAL);
        attr_done = true;
    }

    cvt_x<<<(MTOT * (size_t)DIM) / (256 * 4), 256>>>(X);
    transpose_w<<<dim3(DIM / 32, DIM / 32, 3), 256>>>(Wq, Wk, Wv);
    gemm_tc<0><<<dim3(DIM / BN, MTOT / BM, 3), 128, SMEM_TOTAL>>>(out);
    transpose_v<<<dim3(SEQ / 32, DIM / 32, BATCH), 256>>>(out);
    gemm_tc<1><<<dim3(SEQ / BN, SEQ / BM, BATCH), 128, SMEM_TOTAL>>>(out);
    softmax_rows<<<dim3(SEQ, BATCH), 256>>>();
    gemm_tc<2><<<dim3(DIM / BN, SEQ / BM, BATCH), 128, SMEM_TOTAL>>>(out);
}

// round 11
// speedup vs baseline: 1.8290x; 1.8290x over previous
#include <cuda_runtime.h>
#include <cuda_fp16.h>
#include <math.h>
#include <stdint.h>

// Problem sizes (fixed)
#define BATCH 8
#define SEQ   2048
#define DIM   1024
#define MTOT  (BATCH*SEQ)
#define PLANE (SEQ*DIM)
#define TEN   ((size_t)BATCH*PLANE)

// ---------------- device scratch (no allocations allowed) -------------------
__device__ float  g_scores[(size_t)BATCH * SEQ * SEQ];  // fp32 raw scores (S)
__device__ __half g_Ph[(size_t)BATCH * SEQ * SEQ];      // fp16 probabilities (P)
__device__ __half g_Wh[(size_t)3 * DIM * DIM];          // fp16 W^T [n][k]
__device__ __half g_Vh[(size_t)BATCH * DIM * SEQ];      // fp16 V^T [n][k]
__device__ __half g_Xh[(size_t)MTOT * DIM];             // fp16 X
__device__ __half g_Qh[(size_t)MTOT * DIM];             // fp16 Q
__device__ __half g_Kh[(size_t)MTOT * DIM];             // fp16 K

// ---------------- helpers ----------------------------------------------------
__device__ __forceinline__ uint32_t smem_u32(const void* p) {
    uint32_t a;
    asm("{ .reg .u64 t; cvta.to.shared.u64 t, %1; cvt.u32.u64 %0, t; }" : "=r"(a) : "l"(p));
    return a;
}
__device__ __forceinline__ void cp16(uint32_t s, const void* g) {
    asm volatile("cp.async.cg.shared.global [%0], [%1], 16;" :: "r"(s), "l"(g));
}
__device__ __forceinline__ void cp_commit() { asm volatile("cp.async.commit_group;" ::: "memory"); }
template <int N> __device__ __forceinline__ void cp_wait() {
    asm volatile("cp.async.wait_group %0;" :: "n"(N) : "memory");
}
__device__ __forceinline__ void mma_f16(float* c, const uint32_t* a, const uint32_t* b) {
    asm volatile(
        "mma.sync.aligned.m16n8k16.row.col.f32.f16.f16.f32 "
        "{%0,%1,%2,%3}, {%4,%5,%6,%7}, {%8,%9}, {%0,%1,%2,%3};"
        : "+f"(c[0]), "+f"(c[1]), "+f"(c[2]), "+f"(c[3])
        : "r"(a[0]), "r"(a[1]), "r"(a[2]), "r"(a[3]), "r"(b[0]), "r"(b[1]));
}

// ---------------- GEMM config ------------------------------------------------
#define BM 128
#define BN 128
#define BKH 32                   // K halfs per stage
#define PITCH_H 40               // half pitch; word-stride 20 -> conflict-free
#define STAGES 3
#define ASTG (BM*PITCH_H)        // halfs per A stage
#define BSTG (BN*PITCH_H)
#define SMEM_TOTAL (STAGES*(ASTG+BSTG)*2)   // 61,440 B -> 2+ CTAs/SM

// 128 threads = 4 warps (2 along M x 2 along N), each owns a 64x64 sub-tile.
// MODE 0: QKV  C = Xh * Wh^T
// MODE 1: S    C = Qh * Kh^T (causal blocks, scaled)
// MODE 2: O    C = Ph * Vh^T (causal K length)
template <int MODE>
__global__ __launch_bounds__(128, 2)
void gemm_tc(float* __restrict__ out)
{
    const int bx = blockIdx.x, by = blockIdx.y, bz = blockIdx.z;
    if (MODE == 1 && bx > by) return;

    const __half *A, *B;
    float *C;
    int lda, ldb, ldc, KT;
    float scale = 1.f;

    if (MODE == 0) {
        A = g_Xh + (size_t)by * BM * DIM;                           lda = DIM;
        B = g_Wh + (size_t)bz * DIM * DIM + (size_t)bx * BN * DIM;  ldb = DIM;
        C = out + (size_t)(1 + bz) * TEN + (size_t)by * BM * DIM + bx * BN; ldc = DIM;
        KT = DIM / BKH;
    } else if (MODE == 1) {
        A = g_Qh + (size_t)bz * PLANE + (size_t)by * BM * DIM;      lda = DIM;
        B = g_Kh + (size_t)bz * PLANE + (size_t)bx * BN * DIM;      ldb = DIM;
        C = g_scores + (size_t)bz * SEQ * SEQ + (size_t)by * BM * SEQ + bx * BN; ldc = SEQ;
        KT = DIM / BKH;
        scale = 0.03125f;   // 1/sqrt(1024)
    } else {
        A = g_Ph + (size_t)bz * SEQ * SEQ + (size_t)by * BM * SEQ;  lda = SEQ;
        B = g_Vh + (size_t)bz * DIM * SEQ + (size_t)bx * BN * SEQ;  ldb = SEQ;
        C = out + (size_t)bz * PLANE + (size_t)by * BM * DIM + bx * BN; ldc = DIM;
        KT = (by + 1) * (BM / BKH);
    }

    extern __shared__ __half sm[];
    const uint32_t sb = smem_u32(sm);
    const int tid = threadIdx.x;
    const int lane = tid & 31;
    const int warp = tid >> 5;
    const int warpM = warp & 1;       // 2 warps along M (64 rows)
    const int warpN = warp >> 1;      // 2 warps along N (64 cols)

    float acc[4][8][4];
#pragma unroll
    for (int mt = 0; mt < 4; mt++)
#pragma unroll
        for (int nt = 0; nt < 8; nt++)
#pragma unroll
            for (int i = 0; i < 4; i++) acc[mt][nt][i] = 0.f;

    // Stage tile: rows x 32 halfs; 4 x 16B chunks per row.
    auto load_stage = [&](int st, int k0) {
        const uint32_t sA = sb + (uint32_t)(st * ASTG) * 2;
        const uint32_t sB = sb + (uint32_t)((STAGES * ASTG) + st * BSTG) * 2;
#pragma unroll
        for (int i = 0; i < 4; i++) {              // A: 128 rows x 4 chunks = 512
            int ci = tid + i * 128;
            int r = ci >> 2, ch = ci & 3;
            cp16(sA + (uint32_t)(r * PITCH_H + ch * 8) * 2, A + (size_t)r * lda + k0 + ch * 8);
        }
#pragma unroll
        for (int i = 0; i < 4; i++) {              // B: 128 rows x 4 chunks
            int ci = tid + i * 128;
            int r = ci >> 2, ch = ci & 3;
            cp16(sB + (uint32_t)(r * PITCH_H + ch * 8) * 2, B + (size_t)r * ldb + k0 + ch * 8);
        }
    };

#pragma unroll
    for (int p = 0; p < STAGES - 1; p++) {
        load_stage(p, p * BKH);
        cp_commit();
    }

    for (int it = 0; it < KT; ++it) {
        cp_wait<STAGES - 2>();
        __syncthreads();

        const int nx = it + STAGES - 1;
        if (nx < KT) load_stage(nx % STAGES, nx * BKH);
        cp_commit();

        const int s = it % STAGES;
        const __half* sAf = sm + s * ASTG;
        const __half* sBf = sm + STAGES * ASTG + s * BSTG;

#pragma unroll
        for (int k16 = 0; k16 < BKH / 16; k16++) {
            const int ch = k16 * 16 + 2 * (lane & 3);   // half col of this thread's pair
            uint32_t af[4][4];
            uint32_t bf[8][2];
            const int r0 = warpM * 64 + (lane >> 2);
#pragma unroll
            for (int mt = 0; mt < 4; mt++) {
                const int rr = r0 + mt * 16;
                af[mt][0] = *(const uint32_t*)(sAf + rr * PITCH_H + ch);
                af[mt][1] = *(const uint32_t*)(sAf + (rr + 8) * PITCH_H + ch);
                af[mt][2] = *(const uint32_t*)(sAf + rr * PITCH_H + ch + 8);
                af[mt][3] = *(const uint32_t*)(sAf + (rr + 8) * PITCH_H + ch + 8);
            }
            const int n0 = warpN * 64 + (lane >> 2);
#pragma unroll
            for (int nt = 0; nt < 8; nt++) {
                const int nn = n0 + nt * 8;
                bf[nt][0] = *(const uint32_t*)(sBf + nn * PITCH_H + ch);
                bf[nt][1] = *(const uint32_t*)(sBf + nn * PITCH_H + ch + 8);
            }
#pragma unroll
            for (int mt = 0; mt < 4; mt++)
#pragma unroll
                for (int nt = 0; nt < 8; nt++)
                    mma_f16(acc[mt][nt], af[mt], bf[nt]);
        }
        __syncthreads();
    }

    // ---- epilogue ----
    const int rbase = warpM * 64 + (lane >> 2);
    const int cbase = warpN * 64 + 2 * (lane & 3);
#pragma unroll
    for (int mt = 0; mt < 4; mt++) {
#pragma unroll
        for (int nt = 0; nt < 8; nt++) {
            const int row = rbase + mt * 16;
            const int col = cbase + nt * 8;
            float2 v0 = {acc[mt][nt][0] * scale, acc[mt][nt][1] * scale};
            float2 v1 = {acc[mt][nt][2] * scale, acc[mt][nt][3] * scale};
            *(float2*)(C + (size_t)row * ldc + col)       = v0;
            *(float2*)(C + (size_t)(row + 8) * ldc + col) = v1;

            if (MODE == 0 && bz < 2) {   // emit fp16 Q / K for the score GEMM
                __half* T = (bz == 0 ? g_Qh : g_Kh) +
                            (size_t)(by * BM + row) * DIM + bx * BN + col;
                *(__half2*)T = __floats2half2_rn(v0.x, v0.y);
                *(__half2*)(T + (size_t)8 * DIM) = __floats2half2_rn(v1.x, v1.y);
            }
        }
    }
}

// ---------------- producers --------------------------------------------------
__global__ __launch_bounds__(256)
void cvt_x(const float* __restrict__ X)
{
    size_t i = ((size_t)blockIdx.x * 256 + threadIdx.x) * 4;
    float4 v = *(const float4*)(X + i);
    __half2 h0 = __floats2half2_rn(v.x, v.y);
    __half2 h1 = __floats2half2_rn(v.z, v.w);
    *(__half2*)(g_Xh + i)     = h0;
    *(__half2*)(g_Xh + i + 2) = h1;
}

__global__ __launch_bounds__(256)
void transpose_w(const float* __restrict__ Wq, const float* __restrict__ Wk,
                 const float* __restrict__ Wv)
{
    __shared__ float t[32][33];
    const int w = blockIdx.z;
    const float* W = (w == 0) ? Wq : (w == 1) ? Wk : Wv;
    __half* Wh = g_Wh + (size_t)w * DIM * DIM;
    const int n0 = blockIdx.x * 32, k0 = blockIdx.y * 32;
    const int tx = threadIdx.x & 31, ty = threadIdx.x >> 5;
#pragma unroll
    for (int j = 0; j < 4; j++)
        t[ty * 4 + j][tx] = W[(size_t)(k0 + ty * 4 + j) * DIM + n0 + tx];
    __syncthreads();
#pragma unroll
    for (int j = 0; j < 4; j++)
        Wh[(size_t)(n0 + ty * 4 + j) * DIM + k0 + tx] = __float2half_rn(t[tx][ty * 4 + j]);
}

__global__ __launch_bounds__(256)
void transpose_v(const float* __restrict__ out)
{
    __shared__ float t[32][33];
    const int b = blockIdx.z;
    const float* V = out + 3 * TEN + (size_t)b * PLANE;   // [S][D] fp32
    __half* Vh = g_Vh + (size_t)b * DIM * SEQ;            // [D][S] fp16
    const int s0 = blockIdx.x * 32, a0 = blockIdx.y * 32;
    const int tx = threadIdx.x & 31, ty = threadIdx.x >> 5;
#pragma unroll
    for (int j = 0; j < 4; j++)
        t[ty * 4 + j][tx] = V[(size_t)(s0 + ty * 4 + j) * DIM + a0 + tx];
    __syncthreads();
#pragma unroll
    for (int j = 0; j < 4; j++)
        Vh[(size_t)(a0 + ty * 4 + j) * SEQ + s0 + tx] = __float2half_rn(t[tx][ty * 4 + j]);
}

// ---------------- softmax (reads fp32 S, writes fp16 P) ----------------------
__global__ __launch_bounds__(256)
void softmax_rows()
{
    __shared__ float row[SEQ];
    __shared__ float red[8];
    const int q = blockIdx.x, b = blockIdx.y, tid = threadIdx.x;
    const int lane = tid & 31, warp = tid >> 5;
    const float* Srow = g_scores + (size_t)b * SEQ * SEQ + (size_t)q * SEQ;
    __half* Prow = g_Ph + (size_t)b * SEQ * SEQ + (size_t)q * SEQ;
    const int L = q + 1;
    const int kend = ((q >> 7) + 1) << 7;
    const int L4 = L >> 2;

    float mx = -INFINITY;
    const float4* S4 = (const float4*)Srow;
    for (int i = tid; i < L4; i += 256) {
        float4 v = S4[i];
        *(float4*)&row[i * 4] = v;
        mx = fmaxf(fmaxf(mx, fmaxf(v.x, v.y)), fmaxf(v.z, v.w));
    }
    if (L4 * 4 + tid < L) {
        float v = Srow[L4 * 4 + tid];
        row[L4 * 4 + tid] = v;
        mx = fmaxf(mx, v);
    }
#pragma unroll
    for (int o = 16; o > 0; o >>= 1) mx = fmaxf(mx, __shfl_xor_sync(~0u, mx, o));
    if (lane == 0) red[warp] = mx;
    __syncthreads();
    mx = red[0];
#pragma unroll
    for (int w2 = 1; w2 < 8; w2++) mx = fmaxf(mx, red[w2]);
    __syncthreads();

    float sum = 0.f;
    for (int i = tid; i < L4; i += 256) {
        float4 v = *(float4*)&row[i * 4];
        v.x = __expf(v.x - mx); v.y = __expf(v.y - mx);
        v.z = __expf(v.z - mx); v.w = __expf(v.w - mx);
        *(float4*)&row[i * 4] = v;
        sum += v.x + v.y + v.z + v.w;
    }
    if (L4 * 4 + tid < L) {
        float e = __expf(row[L4 * 4 + tid] - mx);
        row[L4 * 4 + tid] = e;
        sum += e;
    }
#pragma unroll
    for (int o = 16; o > 0; o >>= 1) sum += __shfl_xor_sync(~0u, sum, o);
    if (lane == 0) red[warp] = sum;
    __syncthreads();
    sum = 0.f;
#pragma unroll
    for (int w2 = 0; w2 < 8; w2++) sum += red[w2];
    const float inv = 1.f / sum;

    for (int i = tid; i < L4; i += 256) {
        float4 v = *(float4*)&row[i * 4];
        *(__half2*)(Prow + i * 4)     = __floats2half2_rn(v.x * inv, v.y * inv);
        *(__half2*)(Prow + i * 4 + 2) = __floats2half2_rn(v.z * inv, v.w * inv);
    }
    if (L4 * 4 + tid < L) Prow[L4 * 4 + tid] = __float2half_rn(row[L4 * 4 + tid] * inv);
    for (int i = L + tid; i < kend; i += 256) Prow[i] = __float2half_rn(0.f);
}

// ---------------- launch -----------------------------------------------------
extern "C" void kernel_launch(void* const* d_in, const int* in_sizes, int n_in,
                              void* d_out, int out_size)
{
    const float* X  = (const float*)d_in[0];
    const float* Wq = (const float*)d_in[1];
    const float* Wk = (const float*)d_in[2];
    const float* Wv = (const float*)d_in[3];
    float* out = (float*)d_out;

    static bool attr_done = false;
    if (!attr_done) {
        cudaFuncSetAttribute(gemm_tc<0>, cudaFuncAttributeMaxDynamicSharedMemorySize, SMEM_TOTAL);
        cudaFuncSetAttribute(gemm_tc<1>, cudaFuncAttributeMaxDynamicSharedMemorySize, SMEM_TOTAL);
        cudaFuncSetAttribute(gemm_tc<2>, cudaFuncAttributeMaxDynamicSharedMemorySize, SMEM_TOTAL);
        attr_done = true;
    }

    cvt_x<<<(MTOT * (size_t)DIM) / (256 * 4), 256>>>(X);
    transpose_w<<<dim3(DIM / 32, DIM / 32, 3), 256>>>(Wq, Wk, Wv);
    gemm_tc<0><<<dim3(DIM / BN, MTOT / BM, 3), 128, SMEM_TOTAL>>>(out);
    transpose_v<<<dim3(SEQ / 32, DIM / 32, BATCH), 256>>>(out);
    gemm_tc<1><<<dim3(SEQ / BN, SEQ / BM, BATCH), 128, SMEM_TOTAL>>>(out);
    softmax_rows<<<dim3(SEQ, BATCH), 256>>>();
    gemm_tc<2><<<dim3(DIM / BN, SEQ / BM, BATCH), 128, SMEM_TOTAL>>>(out);
}